// round 4
// baseline (speedup 1.0000x reference)
#include <cuda_runtime.h>
#include <cuda_bf16.h>
#include <cstdint>

// out[row][c] = E[row % 8][c] for row < n, else 0.
// 8-row period = 8*256 fp32 = 8 KB = 512 float4. A 512-thread block holds the
// entire period in registers (one float4/thread) and streams STG.128 with an
// evict-first hint. Pure HBM-write-bound: target ~38-45 us for 268 MB.

#define GROUP_F4 512              // float4 elements per 8-row group (8 KB)
#define FILL_BLOCKS 1024          // divides 32768 groups evenly: 32 groups/block
#define UNROLL 4

__global__ __launch_bounds__(512, 4)
void rpe_fill_kernel(const float4* __restrict__ E4,   // 8*64 = 512 float4
                     float4* __restrict__ out4,
                     int num_groups) {
    const int tid = threadIdx.x;          // 0..511 == (rowmod8*64 + col4)
    const float4 val = E4[tid];           // one load per thread; 8 KB total

    // Block-contiguous partitioning: block b owns groups [g0, g1).
    const int per_block = (num_groups + gridDim.x - 1) / gridDim.x;
    const int g0 = blockIdx.x * per_block;
    int g1 = g0 + per_block;
    if (g1 > num_groups) g1 = num_groups;

    float4* p = out4 + (size_t)g0 * GROUP_F4 + tid;
    int g = g0;

    // Unrolled main: 4 independent STG.128 per branch, 32 KB contiguous span.
    for (; g + UNROLL <= g1; g += UNROLL, p += UNROLL * GROUP_F4) {
        __stcs(p + 0 * GROUP_F4, val);
        __stcs(p + 1 * GROUP_F4, val);
        __stcs(p + 2 * GROUP_F4, val);
        __stcs(p + 3 * GROUP_F4, val);
    }
    for (; g < g1; ++g, p += GROUP_F4) {
        __stcs(p, val);
    }
}

// Tail: rows [start_row, total_rows). Pattern for row < n, zeros otherwise.
// Not launched when n fills the output with whole groups (the bench shape).
__global__ void rpe_tail_kernel(const float4* __restrict__ E4,
                                float4* __restrict__ out4,
                                int start_row, int total_rows, int n) {
    const int row = start_row + blockIdx.x;   // one block per tail row
    if (row >= total_rows) return;
    const int c = threadIdx.x;                // 0..63 float4 columns
    float4 v;
    if (row < n) {
        v = E4[((row & 7) << 6) | c];
    } else {
        v = make_float4(0.f, 0.f, 0.f, 0.f);
    }
    out4[(size_t)row * 64 + c] = v;
}

extern "C" void kernel_launch(void* const* d_in, const int* in_sizes, int n_in,
                              void* d_out, int out_size) {
    // metadata order: d_in[0] = x (int32, len n; values unused),
    //                 d_in[1] = E_relative_position (float32, 8*256)
    const float4* E4 = (const float4*)d_in[1];
    float4* out4 = (float4*)d_out;

    const int total_rows = out_size / 256;     // 262144
    int n = in_sizes[0];
    if (n > total_rows) n = total_rows;        // never store past d_out
    if (n < 0) n = 0;

    const int full_groups = n / 8;             // 32768 when n == 262144

    if (full_groups > 0) {
        int grid = full_groups < FILL_BLOCKS ? full_groups : FILL_BLOCKS;
        rpe_fill_kernel<<<grid, 512>>>(E4, out4, full_groups);
    }

    const int start_row = full_groups * 8;
    const int tail_rows = total_rows - start_row;
    if (tail_rows > 0) {
        rpe_tail_kernel<<<tail_rows, 64>>>(E4, out4, start_row, total_rows, n);
    }
}